// round 5
// baseline (speedup 1.0000x reference)
#include <cuda_runtime.h>
#include <math.h>

// GRU recurrence, persistent kernel, round 4.
// B=256, T=2048, H=150 (3H=450 gate rows), I=O=1.
// 128 CTAs x 512 threads. CTA owns batches (2*cta, 2*cta+1).
// The CTA is split into TWO INDEPENDENT 256-thread groups, one batch each,
// synchronized by named barriers (bar.sync 1/2, 256) so the groups slip in
// time and hide each other's gate/barrier bubbles.
// Thread lt (=tid&255) in a group owns gate-rows lt and lt+256 for its batch.
// W_hh per row: k in [0,84) in registers (packed f32x2), k in [84,152) in SMEM
// (shared by both groups). Matvec uses fma.rn.f32x2.

#define NTHREADS 512
#define NGRP     256
#define NROWS    512
#define HID      150
#define G3       450
#define TLEN     2048
#define KREG     84            // floats of W per row in registers (42 u64 pairs)
#define NGREG    21            // 4-float k-groups from registers
#define NGSM     17            // 4-float k-groups from SMEM (k = 84..151)

// SMEM layout (floats):
#define OFF_SW   0                          // ulonglong2 [NGSM][NROWS] = 34816 floats
#define OFF_SX0  (NGSM*NROWS*4)             // 2048
#define OFF_SX1  (OFF_SX0 + TLEN)           // 2048
#define OFF_H0   (OFF_SX1 + TLEN)           // 160
#define OFF_H1   (OFF_H0 + 160)             // 160
#define OFF_GH0  (OFF_H1 + 160)             // 512
#define OFF_GH1  (OFF_GH0 + NROWS)          // 512
#define OFF_PX   (OFF_GH1 + NROWS)          // 160
#define OFF_PY   (OFF_PX + 160)             // 160
#define SMEM_FLOATS (OFF_PY + 160)          // 40576 floats = 162,304 B

typedef unsigned long long u64;

#define FFMA2(d, a, b) asm("fma.rn.f32x2 %0, %1, %2, %0;" : "+l"(d) : "l"(a), "l"(b))
#define BARG(id)       asm volatile("bar.sync %0, %1;" :: "r"(id), "n"(NGRP) : "memory")

__device__ __forceinline__ u64 pack2(float a, float b) {
    u64 r; asm("mov.b64 %0, {%1, %2};" : "=l"(r) : "f"(a), "f"(b)); return r;
}
__device__ __forceinline__ float rsum2(u64 v) {
    float lo, hi; asm("mov.b64 {%0, %1}, %2;" : "=f"(lo), "=f"(hi) : "l"(v));
    return lo + hi;
}
__device__ __forceinline__ float sigf(float v) {
    return 1.0f / (1.0f + __expf(-v));
}
__device__ __forceinline__ float tanhfast(float v) {
    float e = __expf(-2.0f * v);
    return __fdividef(1.0f - e, 1.0f + e);
}

extern "C" __global__ void __launch_bounds__(NTHREADS, 1)
gru_persistent(const float* __restrict__ x,     // [B][T]
               const float* __restrict__ Wih,   // [450][1]
               const float* __restrict__ Whh,   // [450][150]
               const float* __restrict__ bih,   // [450]
               const float* __restrict__ bhh,   // [450]
               const float* __restrict__ Wlin,  // [1][150]
               const float* __restrict__ blin,  // [1]
               float* __restrict__ out)         // [B][T]
{
    extern __shared__ float smem[];
    ulonglong2* sWv = (ulonglong2*)(smem + OFF_SW);   // [NGSM][NROWS]

    const int tid = threadIdx.x;
    const int grp = tid >> 8;          // 0 or 1 -> which batch
    const int lt  = tid & (NGRP - 1);  // index within group
    const int r0  = lt;
    const int r1  = lt + NGRP;
    const int bat = blockIdx.x * 2 + grp;
    const int bid = 1 + grp;           // named barrier id for this group

    // per-group views
    float* sx  = smem + (grp ? OFF_SX1 : OFF_SX0);
    float* hs  = smem + (grp ? OFF_H1  : OFF_H0);
    float* gh  = smem + (grp ? OFF_GH1 : OFF_GH0);
    float* pb  = smem + (grp ? OFF_PY  : OFF_PX);
    const ulonglong2* hv = (const ulonglong2*)hs;     // [40]

    // ---------------- init ----------------
    u64 w0[KREG / 2], w1[KREG / 2];
    {
        const float* wr0 = Whh + r0 * HID;
        const float* wr1 = Whh + r1 * HID;
        #pragma unroll
        for (int p = 0; p < KREG / 2; p++) {
            int k = 2 * p;
            float a0 = wr0[k];                      // r0 < 256 < 450 always valid
            float a1 = wr0[k + 1];
            float c0 = (r1 < G3) ? wr1[k]     : 0.0f;
            float c1 = (r1 < G3) ? wr1[k + 1] : 0.0f;
            w0[p] = pack2(a0, a1);
            w1[p] = pack2(c0, c1);
        }
        if (grp == 0) {   // SMEM W shared by both groups: write once
            #pragma unroll
            for (int gs = 0; gs < NGSM; gs++) {
                int k = KREG + 4 * gs;
                float4 v0, v1;
                v0.x = (k + 0 < HID) ? wr0[k + 0] : 0.0f;
                v0.y = (k + 1 < HID) ? wr0[k + 1] : 0.0f;
                v0.z = (k + 2 < HID) ? wr0[k + 2] : 0.0f;
                v0.w = (k + 3 < HID) ? wr0[k + 3] : 0.0f;
                v1.x = (r1 < G3 && k + 0 < HID) ? wr1[k + 0] : 0.0f;
                v1.y = (r1 < G3 && k + 1 < HID) ? wr1[k + 1] : 0.0f;
                v1.z = (r1 < G3 && k + 2 < HID) ? wr1[k + 2] : 0.0f;
                v1.w = (r1 < G3 && k + 3 < HID) ? wr1[k + 3] : 0.0f;
                ((float4*)sWv)[gs * NROWS + r0] = v0;
                ((float4*)sWv)[gs * NROWS + r1] = v1;
            }
        }
    }

    // Per-row bias / input weight. Rows >= 300 (n-gate) carry b_hh only in the
    // matvec; i_n = x*W_ih + b_ih enters at the gate stage.
    float wih0, bias0, wih1 = 0.0f, bias1 = 0.0f;
    wih0  = (r0 < 2 * HID) ? Wih[r0] : 0.0f;
    bias0 = (r0 < 2 * HID) ? (bih[r0] + bhh[r0]) : bhh[r0];
    if (r1 < G3) {
        wih1  = (r1 < 2 * HID) ? Wih[r1] : 0.0f;
        bias1 = (r1 < 2 * HID) ? (bih[r1] + bhh[r1]) : bhh[r1];
    }

    float win = 0.0f, bin = 0.0f, wlin = 0.0f;
    if (lt < HID) {
        win  = Wih[2 * HID + lt];
        bin  = bih[2 * HID + lt];
        wlin = Wlin[lt];
    }
    const float bl = __ldg(blin);

    // Stage this group's x row into SMEM; zero h (incl. pad)
    const float* xr = x + (size_t)bat * TLEN;
    for (int i = lt; i < TLEN; i += NGRP) sx[i] = xr[i];
    for (int i = lt; i < 160;  i += NGRP) hs[i] = 0.0f;
    __syncthreads();   // full-CTA once: sW + x + h visible to everyone

    float* orow = out + (size_t)bat * TLEN;

    // ---------------- time loop (group-local sync only) ----------------
    for (int t = 0; t < TLEN; t++) {
        const float xt = sx[t];

        u64 a0x = 0, a0y = 0, a1x = 0, a1y = 0;

        // k = 0..83 : W in registers, h via broadcast LDS.128
        #pragma unroll
        for (int g = 0; g < NGREG; g++) {
            const ulonglong2 q = hv[g];
            FFMA2(a0x, w0[2 * g],     q.x);
            FFMA2(a1x, w1[2 * g],     q.x);
            FFMA2(a0y, w0[2 * g + 1], q.y);
            FFMA2(a1y, w1[2 * g + 1], q.y);
        }
        // k = 84..151 : W in SMEM (lane-consecutive, conflict-free)
        #pragma unroll
        for (int gs = 0; gs < NGSM; gs++) {
            const ulonglong2 wv0 = sWv[gs * NROWS + r0];
            const ulonglong2 wv1 = sWv[gs * NROWS + r1];
            const ulonglong2 q   = hv[NGREG + gs];
            FFMA2(a0x, wv0.x, q.x);
            FFMA2(a1x, wv1.x, q.x);
            FFMA2(a0y, wv0.y, q.y);
            FFMA2(a1y, wv1.y, q.y);
        }

        gh[r0] = rsum2(a0x) + rsum2(a0y) + fmaf(xt, wih0, bias0);
        gh[r1] = rsum2(a1x) + rsum2(a1y) + fmaf(xt, wih1, bias1);
        BARG(bid);

        // gate stage: thread u < 150 of this group updates hidden unit u
        if (lt < HID) {
            const float gr = gh[lt];
            const float gz = gh[lt + HID];
            const float gn = gh[lt + 2 * HID];
            const float h  = hs[lt];

            const float in = fmaf(xt, win, bin);
            const float r  = sigf(gr);
            const float z  = sigf(gz);
            const float n  = tanhfast(fmaf(r, gn, in));
            const float hn = fmaxf(0.0f, fmaf(z, h - n, n));

            hs[lt] = hn;
            pb[lt] = hn * wlin;
        }
        BARG(bid);

        // y head: group's warp 0 reduces (overlaps other warps' next matvec)
        if (lt < 32) {
            const int lane = lt;
            float s = pb[lane] + pb[lane + 32] + pb[lane + 64] + pb[lane + 96]
                    + ((lane + 128 < HID) ? pb[lane + 128] : 0.0f);
            s += __shfl_xor_sync(0xffffffffu, s, 16);
            s += __shfl_xor_sync(0xffffffffu, s, 8);
            s += __shfl_xor_sync(0xffffffffu, s, 4);
            s += __shfl_xor_sync(0xffffffffu, s, 2);
            s += __shfl_xor_sync(0xffffffffu, s, 1);
            if (lane == 0) orow[t] = s + bl;
        }
    }
}

extern "C" void kernel_launch(void* const* d_in, const int* in_sizes, int n_in,
                              void* d_out, int out_size) {
    const float* x    = (const float*)d_in[0];
    const float* Wih  = (const float*)d_in[1];
    const float* Whh  = (const float*)d_in[2];
    const float* bih  = (const float*)d_in[3];
    const float* bhh  = (const float*)d_in[4];
    const float* Wlin = (const float*)d_in[5];
    const float* blin = (const float*)d_in[6];
    float* out = (float*)d_out;

    const size_t smem_bytes = SMEM_FLOATS * sizeof(float);   // 162,304 B
    cudaFuncSetAttribute(gru_persistent,
                         cudaFuncAttributeMaxDynamicSharedMemorySize,
                         (int)smem_bytes);

    gru_persistent<<<128, NTHREADS, smem_bytes>>>(x, Wih, Whh, bih, bhh, Wlin, blin, out);
}

// round 7
// speedup vs baseline: 2.6413x; 2.6413x over previous
#include <cuda_runtime.h>
#include <math.h>

// GRU recurrence, persistent kernel, round 5: K-split warp doubling.
// B=256, T=2048, H=150 (3H=450 gate rows), I=O=1.
// 128 CTAs x 512 threads; CTA owns batches (2*cta, 2*cta+1). BOTH thread groups
// work on BOTH batches, but each group owns HALF of the K range:
//   group A (tid<256):  k = 0..75      group B (tid>=256): k = 76..151
// Thread lt (=tid&255) owns gate-rows lt and lt+256 (rows padded to 512).
// Per row-half: 36 W floats in registers (18 u64 f32x2 pairs), 40 in SMEM.
// Partial dot products summed in the gate stage (pA + pB).

#define NTH     512
#define NGRP    256
#define NROWS   512
#define HID     150
#define G3      450
#define TLEN    2048
#define KH      76         // K per half (152 padded total)
#define KRH     36         // reg floats per half per row (18 u64)
#define NGR     9          // 4-float reg groups per half
#define NSM     10         // 4-float smem groups per half (40 floats)

// SMEM layout (floats):
#define OFF_SW   0                          // ulonglong2 [2*NSM][NROWS] = 40960 floats
#define OFF_SX0  (2*NSM*NROWS*4)            // 2048
#define OFF_SX1  (OFF_SX0 + TLEN)           // 2048
#define OFF_H0   (OFF_SX1 + TLEN)           // 160
#define OFF_H1   (OFF_H0 + 160)             // 160
#define OFF_PA0  (OFF_H1 + 160)             // 512  (group A partial, batch 0)
#define OFF_PA1  (OFF_PA0 + NROWS)          // 512
#define OFF_PB0  (OFF_PA1 + NROWS)          // 512  (group B partial, batch 0)
#define OFF_PB1  (OFF_PB0 + NROWS)          // 512
#define OFF_Y0   (OFF_PB1 + NROWS)         // 160
#define OFF_Y1   (OFF_Y0 + 160)            // 160
#define SMEM_FLOATS (OFF_Y1 + 160)         // 47744 floats = 190,976 B

typedef unsigned long long u64;

#define FFMA2(d, a, b) asm("fma.rn.f32x2 %0, %1, %2, %0;" : "+l"(d) : "l"(a), "l"(b))

__device__ __forceinline__ u64 pack2(float a, float b) {
    u64 r; asm("mov.b64 %0, {%1, %2};" : "=l"(r) : "f"(a), "f"(b)); return r;
}
__device__ __forceinline__ float rsum2(u64 v) {
    float lo, hi; asm("mov.b64 {%0, %1}, %2;" : "=f"(lo), "=f"(hi) : "l"(v));
    return lo + hi;
}
__device__ __forceinline__ float sigf(float v) {
    return 1.0f / (1.0f + __expf(-v));
}
__device__ __forceinline__ float tanhfast(float v) {
    float e = __expf(-2.0f * v);
    return __fdividef(1.0f - e, 1.0f + e);
}

extern "C" __global__ void __launch_bounds__(NTH, 1)
gru_persistent(const float* __restrict__ x,     // [B][T]
               const float* __restrict__ Wih,   // [450][1]
               const float* __restrict__ Whh,   // [450][150]
               const float* __restrict__ bih,   // [450]
               const float* __restrict__ bhh,   // [450]
               const float* __restrict__ Wlin,  // [1][150]
               const float* __restrict__ blin,  // [1]
               float* __restrict__ out)         // [B][T]
{
    extern __shared__ float smem[];
    ulonglong2* sWv = (ulonglong2*)(smem + OFF_SW);   // [(grp*NSM+gs)][NROWS]
    float* sx0 = smem + OFF_SX0;
    float* sx1 = smem + OFF_SX1;
    float* h0s = smem + OFF_H0;
    float* h1s = smem + OFF_H1;
    float* pA0 = smem + OFF_PA0;
    float* pA1 = smem + OFF_PA1;
    float* pB0 = smem + OFF_PB0;
    float* pB1 = smem + OFF_PB1;
    float* y0  = smem + OFF_Y0;
    float* y1  = smem + OFF_Y1;
    const ulonglong2* h0v = (const ulonglong2*)h0s;   // 16B groups of h (batch 0)
    const ulonglong2* h1v = (const ulonglong2*)h1s;

    const int tid = threadIdx.x;
    const int grp = tid >> 8;            // 0: k=0..75,  1: k=76..151
    const int lt  = tid & (NGRP - 1);
    const int r0  = lt;
    const int r1  = lt + NGRP;
    const int b0  = blockIdx.x * 2;
    const int kb  = grp * KH;            // k base for this half
    const int hb  = grp * (KH / 4);      // ulonglong2 base into h arrays (19)

    // ---------------- init: distribute W ----------------
    u64 w0[KRH / 2], w1[KRH / 2];
    {
        const float* wr0 = Whh + r0 * HID + kb;
        const float* wr1 = Whh + r1 * HID + kb;
        #pragma unroll
        for (int p = 0; p < KRH / 2; p++) {   // k = kb .. kb+35, always < 150
            int k = 2 * p;
            float a0 = wr0[k];
            float a1 = wr0[k + 1];
            float c0 = (r1 < G3) ? wr1[k]     : 0.0f;
            float c1 = (r1 < G3) ? wr1[k + 1] : 0.0f;
            w0[p] = pack2(a0, a1);
            w1[p] = pack2(c0, c1);
        }
        // SMEM part: k = kb+36 .. kb+75 (k >= 150 zero-padded)
        #pragma unroll
        for (int gs = 0; gs < NSM; gs++) {
            int k = KRH + 4 * gs;
            float4 v0, v1;
            v0.x = (kb + k + 0 < HID) ? wr0[k + 0] : 0.0f;
            v0.y = (kb + k + 1 < HID) ? wr0[k + 1] : 0.0f;
            v0.z = (kb + k + 2 < HID) ? wr0[k + 2] : 0.0f;
            v0.w = (kb + k + 3 < HID) ? wr0[k + 3] : 0.0f;
            v1.x = (r1 < G3 && kb + k + 0 < HID) ? wr1[k + 0] : 0.0f;
            v1.y = (r1 < G3 && kb + k + 1 < HID) ? wr1[k + 1] : 0.0f;
            v1.z = (r1 < G3 && kb + k + 2 < HID) ? wr1[k + 2] : 0.0f;
            v1.w = (r1 < G3 && kb + k + 3 < HID) ? wr1[k + 3] : 0.0f;
            ((float4*)sWv)[(grp * NSM + gs) * NROWS + r0] = v0;
            ((float4*)sWv)[(grp * NSM + gs) * NROWS + r1] = v1;
        }
    }

    // Per-row input weight / bias — only group A adds these to its partial.
    // Rows >= 300 (n-gate) carry b_hh only in the matvec; i_n enters at gates.
    float wih0 = 0.0f, bias0 = 0.0f, wih1 = 0.0f, bias1 = 0.0f;
    if (grp == 0) {
        wih0  = (r0 < 2 * HID) ? Wih[r0] : 0.0f;
        bias0 = (r0 < 2 * HID) ? (bih[r0] + bhh[r0]) : bhh[r0];
        if (r1 < G3) {
            wih1  = (r1 < 2 * HID) ? Wih[r1] : 0.0f;
            bias1 = (r1 < 2 * HID) ? (bih[r1] + bhh[r1]) : bhh[r1];
        }
    }

    // Gate-stage constants (lt < 150, both groups: group g handles batch g)
    float win = 0.0f, bin = 0.0f, wlin = 0.0f;
    if (lt < HID) {
        win  = Wih[2 * HID + lt];
        bin  = bih[2 * HID + lt];
        wlin = Wlin[lt];
    }
    const float bl = __ldg(blin);

    // Stage x rows, zero h (incl. pads)
    const float* xr0 = x + (size_t)b0 * TLEN;
    const float* xr1 = x + (size_t)(b0 + 1) * TLEN;
    for (int i = tid; i < TLEN; i += NTH) { sx0[i] = xr0[i]; sx1[i] = xr1[i]; }
    for (int i = tid; i < 160;  i += NTH) { h0s[i] = 0.0f; h1s[i] = 0.0f; }
    __syncthreads();

    float* or0 = out + (size_t)b0 * TLEN;
    float* or1 = out + (size_t)(b0 + 1) * TLEN;

    // ---------------- time loop ----------------
    for (int t = 0; t < TLEN; t++) {
        const float x0 = sx0[t];
        const float x1 = sx1[t];

        u64 a00 = 0, a01 = 0, a10 = 0, a11 = 0;   // a[row][batch]

        // reg part: k = kb .. kb+35
        #pragma unroll
        for (int g = 0; g < NGR; g++) {
            const ulonglong2 q0 = h0v[hb + g];
            const ulonglong2 q1 = h1v[hb + g];
            FFMA2(a00, w0[2 * g],     q0.x);
            FFMA2(a01, w0[2 * g],     q1.x);
            FFMA2(a10, w1[2 * g],     q0.x);
            FFMA2(a11, w1[2 * g],     q1.x);
            FFMA2(a00, w0[2 * g + 1], q0.y);
            FFMA2(a01, w0[2 * g + 1], q1.y);
            FFMA2(a10, w1[2 * g + 1], q0.y);
            FFMA2(a11, w1[2 * g + 1], q1.y);
        }
        // smem part: k = kb+36 .. kb+75
        #pragma unroll
        for (int gs = 0; gs < NSM; gs++) {
            const ulonglong2 wv0 = sWv[(grp * NSM + gs) * NROWS + r0];
            const ulonglong2 wv1 = sWv[(grp * NSM + gs) * NROWS + r1];
            const ulonglong2 q0  = h0v[hb + NGR + gs];
            const ulonglong2 q1  = h1v[hb + NGR + gs];
            FFMA2(a00, wv0.x, q0.x);
            FFMA2(a01, wv0.x, q1.x);
            FFMA2(a10, wv1.x, q0.x);
            FFMA2(a11, wv1.x, q1.x);
            FFMA2(a00, wv0.y, q0.y);
            FFMA2(a01, wv0.y, q1.y);
            FFMA2(a10, wv1.y, q0.y);
            FFMA2(a11, wv1.y, q1.y);
        }

        if (grp == 0) {
            pA0[r0] = rsum2(a00) + fmaf(x0, wih0, bias0);
            pA1[r0] = rsum2(a01) + fmaf(x1, wih0, bias0);
            pA0[r1] = rsum2(a10) + fmaf(x0, wih1, bias1);
            pA1[r1] = rsum2(a11) + fmaf(x1, wih1, bias1);
        } else {
            pB0[r0] = rsum2(a00);
            pB1[r0] = rsum2(a01);
            pB0[r1] = rsum2(a10);
            pB1[r1] = rsum2(a11);
        }
        __syncthreads();

        // gate stage: group g's threads lt<150 handle batch g, unit lt
        if (lt < HID) {
            const float* pa = grp ? pA1 : pA0;
            const float* pp = grp ? pB1 : pB0;
            float*       hs = grp ? h1s : h0s;
            float*       yb = grp ? y1  : y0;
            const float  xt = grp ? x1  : x0;

            const float gr = pa[lt]           + pp[lt];
            const float gz = pa[lt + HID]     + pp[lt + HID];
            const float gn = pa[lt + 2 * HID] + pp[lt + 2 * HID];
            const float h  = hs[lt];

            const float in = fmaf(xt, win, bin);
            const float r  = sigf(gr);
            const float z  = sigf(gz);
            const float n  = tanhfast(fmaf(r, gn, in));
            const float hn = fmaxf(0.0f, fmaf(z, h - n, n));

            hs[lt] = hn;
            yb[lt] = hn * wlin;
        }
        __syncthreads();

        // y head: each group's warp 0 reduces its batch (overlaps next matvec)
        if (lt < 32) {
            const float* yb = grp ? y1 : y0;
            const int lane = lt;
            float s = yb[lane] + yb[lane + 32] + yb[lane + 64] + yb[lane + 96]
                    + ((lane + 128 < HID) ? yb[lane + 128] : 0.0f);
            s += __shfl_xor_sync(0xffffffffu, s, 16);
            s += __shfl_xor_sync(0xffffffffu, s, 8);
            s += __shfl_xor_sync(0xffffffffu, s, 4);
            s += __shfl_xor_sync(0xffffffffu, s, 2);
            s += __shfl_xor_sync(0xffffffffu, s, 1);
            if (lane == 0) (grp ? or1 : or0)[t] = s + bl;
        }
    }
}

extern "C" void kernel_launch(void* const* d_in, const int* in_sizes, int n_in,
                              void* d_out, int out_size) {
    const float* x    = (const float*)d_in[0];
    const float* Wih  = (const float*)d_in[1];
    const float* Whh  = (const float*)d_in[2];
    const float* bih  = (const float*)d_in[3];
    const float* bhh  = (const float*)d_in[4];
    const float* Wlin = (const float*)d_in[5];
    const float* blin = (const float*)d_in[6];
    float* out = (float*)d_out;

    const size_t smem_bytes = SMEM_FLOATS * sizeof(float);   // 190,976 B
    cudaFuncSetAttribute(gru_persistent,
                         cudaFuncAttributeMaxDynamicSharedMemorySize,
                         (int)smem_bytes);

    gru_persistent<<<128, NTH, smem_bytes>>>(x, Wih, Whh, bih, bhh, Wlin, blin, out);
}

// round 8
// speedup vs baseline: 2.8421x; 1.0760x over previous
#include <cuda_runtime.h>
#include <math.h>

// GRU recurrence, persistent kernel, round 7: warp-granular work assignment.
// B=256, T=2048, H=150 (3H=450 gate rows), I=O=1.
// 128 CTAs x 512 threads; CTA owns batches (2*cta, 2*cta+1).
// Two K-half groups of 256 threads (8 warps): grp 0 k=0..75, grp 1 k=76..151.
// Warps 0-6 of each group (lt<224): rows lt and lt+224 (covers rows 0..447).
// Warp 7 of each group: mini-matvec for rows 448,449 (k spread over lanes),
// then the y-head reduction after the gate stage.
// Per main thread: 36 W floats/row in regs (f32x2 pairs), 40/row in SMEM.

#define NTH     512
#define NGRP    256
#define HID     150
#define G2      300
#define TLEN    2048
#define KH      76         // K per half (152 padded)
#define KRH     36         // reg W floats per half-row (18 u64)
#define NGR     9          // 4-float reg k-groups
#define NSM     10         // 4-float smem k-groups (40 floats)
#define NMROW   448        // rows covered by main warps

// SMEM layout (floats):
#define OFF_SW   0                          // float4 [20][448] = 35840 floats
#define OFF_SX   (20*NMROW*4)               // float2[2048] = 4096
#define OFF_H0   (OFF_SX + 2*TLEN)          // 160
#define OFF_H1   (OFF_H0 + 160)             // 160
#define OFF_PA   (OFF_H1 + 160)             // float2[452] = 904
#define OFF_PB   (OFF_PA + 904)             // float2[452] = 904
#define OFF_Y0   (OFF_PB + 904)             // 160
#define OFF_Y1   (OFF_Y0 + 160)             // 160
#define SMEM_FLOATS (OFF_Y1 + 160)          // 42384 floats = 169,536 B

typedef unsigned long long u64;

#define FFMA2(d, a, b) asm("fma.rn.f32x2 %0, %1, %2, %0;" : "+l"(d) : "l"(a), "l"(b))

__device__ __forceinline__ u64 pack2(float a, float b) {
    u64 r; asm("mov.b64 %0, {%1, %2};" : "=l"(r) : "f"(a), "f"(b)); return r;
}
__device__ __forceinline__ float rsum2(u64 v) {
    float lo, hi; asm("mov.b64 {%0, %1}, %2;" : "=f"(lo), "=f"(hi) : "l"(v));
    return lo + hi;
}
__device__ __forceinline__ float tanha(float x) {       // MUFU.TANH
    float y; asm("tanh.approx.f32 %0, %1;" : "=f"(y) : "f"(x)); return y;
}
__device__ __forceinline__ float sigt(float v) {        // sigmoid via tanh.approx
    return fmaf(0.5f, tanha(0.5f * v), 0.5f);
}
__device__ __forceinline__ float tanhacc(float v) {     // accurate fast tanh
    float e = __expf(-2.0f * v);
    return __fdividef(1.0f - e, 1.0f + e);
}

extern "C" __global__ void __launch_bounds__(NTH, 1)
gru_persistent(const float* __restrict__ x,     // [B][T]
               const float* __restrict__ Wih,   // [450][1]
               const float* __restrict__ Whh,   // [450][150]
               const float* __restrict__ bih,   // [450]
               const float* __restrict__ bhh,   // [450]
               const float* __restrict__ Wlin,  // [1][150]
               const float* __restrict__ blin,  // [1]
               float* __restrict__ out)         // [B][T]
{
    extern __shared__ float smem[];
    float4* sW4 = (float4*)(smem + OFF_SW);     // [(grp*NSM+gs)*NMROW + row]
    float2* sxp = (float2*)(smem + OFF_SX);     // (x_b0, x_b1) per t
    float*  h0s = smem + OFF_H0;
    float*  h1s = smem + OFF_H1;
    float2* pA  = (float2*)(smem + OFF_PA);     // group A partial, (b0,b1) per row
    float2* pB  = (float2*)(smem + OFF_PB);
    float*  y0  = smem + OFF_Y0;
    float*  y1  = smem + OFF_Y1;
    const ulonglong2* h0v = (const ulonglong2*)h0s;
    const ulonglong2* h1v = (const ulonglong2*)h1s;

    const int tid  = threadIdx.x;
    const int grp  = tid >> 8;            // 0: k=0..75,  1: k=76..151
    const int lt   = tid & (NGRP - 1);
    const int b0   = blockIdx.x * 2;
    const int kb   = grp * KH;
    const int hb   = grp * (KH / 4);      // ulonglong2 base (19 per half)
    const bool mainw = (lt < 224);
    const int r0   = lt;                  // main rows
    const int r1   = lt + 224;
    const int ly   = lt - 224;            // warp-7 lane role

    // ---------------- init ----------------
    u64 w0[KRH / 2], w1[KRH / 2];         // main-thread reg W (packed k-pairs)
    float m448[4], m449[4];               // warp-7 mini W
    float b448 = 0.0f, b449 = 0.0f;

    if (mainw) {
        const float* wr0 = Whh + r0 * HID + kb;
        const float* wr1 = Whh + r1 * HID + kb;
        #pragma unroll
        for (int p = 0; p < KRH / 2; p++) {       // k = kb..kb+35 < 150 always
            w0[p] = pack2(wr0[2 * p], wr0[2 * p + 1]);
            w1[p] = pack2(wr1[2 * p], wr1[2 * p + 1]);
        }
        #pragma unroll
        for (int gs = 0; gs < NSM; gs++) {        // k = kb+36 .. kb+75 (pad >=150)
            int k = KRH + 4 * gs;
            float4 v0, v1;
            v0.x = (kb + k + 0 < HID) ? wr0[k + 0] : 0.0f;
            v0.y = (kb + k + 1 < HID) ? wr0[k + 1] : 0.0f;
            v0.z = (kb + k + 2 < HID) ? wr0[k + 2] : 0.0f;
            v0.w = (kb + k + 3 < HID) ? wr0[k + 3] : 0.0f;
            v1.x = (kb + k + 0 < HID) ? wr1[k + 0] : 0.0f;
            v1.y = (kb + k + 1 < HID) ? wr1[k + 1] : 0.0f;
            v1.z = (kb + k + 2 < HID) ? wr1[k + 2] : 0.0f;
            v1.w = (kb + k + 3 < HID) ? wr1[k + 3] : 0.0f;
            sW4[(grp * NSM + gs) * NMROW + r0] = v0;
            sW4[(grp * NSM + gs) * NMROW + r1] = v1;
        }
    } else {
        #pragma unroll
        for (int j = 0; j < 4; j++) {
            int k = kb + 4 * ly + j;               // ly in [0,32); valid work ly<19
            bool ok = (ly < 19) && (k < HID);
            m448[j] = ok ? Whh[448 * HID + k] : 0.0f;
            m449[j] = ok ? Whh[449 * HID + k] : 0.0f;
        }
        b448 = bhh[448];
        b449 = bhh[449];
    }

    // Per-row input weight / bias (added by group A only).
    // Rows >= 300 (n-gate) carry b_hh only; i_n enters at the gate stage.
    float wih0 = 0.0f, bias0 = 0.0f, wih1 = 0.0f, bias1 = 0.0f;
    if (grp == 0 && mainw) {
        wih0  = (r0 < G2) ? Wih[r0] : 0.0f;
        bias0 = (r0 < G2) ? (bih[r0] + bhh[r0]) : bhh[r0];
        wih1  = (r1 < G2) ? Wih[r1] : 0.0f;
        bias1 = (r1 < G2) ? (bih[r1] + bhh[r1]) : bhh[r1];
    }

    // Gate-stage constants (lt < 150; group g handles batch g)
    float win = 0.0f, bin = 0.0f, wlin = 0.0f;
    if (lt < HID) {
        win  = Wih[2 * HID + lt];
        bin  = bih[2 * HID + lt];
        wlin = Wlin[lt];
    }
    const float bl = __ldg(blin);

    // Stage x (packed per-t), zero h (incl. pads)
    const float* xr0 = x + (size_t)b0 * TLEN;
    const float* xr1 = x + (size_t)(b0 + 1) * TLEN;
    for (int i = tid; i < TLEN; i += NTH) sxp[i] = make_float2(xr0[i], xr1[i]);
    for (int i = tid; i < 160;  i += NTH) { h0s[i] = 0.0f; h1s[i] = 0.0f; }
    __syncthreads();

    float* or0 = out + (size_t)b0 * TLEN;
    float* or1 = out + (size_t)(b0 + 1) * TLEN;

    // ---------------- time loop ----------------
    for (int t = 0; t < TLEN; t++) {
        const float2 xt = sxp[t];

        if (mainw) {
            u64 a00 = 0, a01 = 0, a10 = 0, a11 = 0;   // a[row][batch]
            #pragma unroll
            for (int g = 0; g < NGR; g++) {            // k = kb .. kb+35 (regs)
                const ulonglong2 q0 = h0v[hb + g];
                const ulonglong2 q1 = h1v[hb + g];
                FFMA2(a00, w0[2 * g],     q0.x);
                FFMA2(a01, w0[2 * g],     q1.x);
                FFMA2(a10, w1[2 * g],     q0.x);
                FFMA2(a11, w1[2 * g],     q1.x);
                FFMA2(a00, w0[2 * g + 1], q0.y);
                FFMA2(a01, w0[2 * g + 1], q1.y);
                FFMA2(a10, w1[2 * g + 1], q0.y);
                FFMA2(a11, w1[2 * g + 1], q1.y);
            }
            #pragma unroll
            for (int gs = 0; gs < NSM; gs++) {         // k = kb+36 .. kb+75 (smem)
                const ulonglong2 wv0 = ((const ulonglong2*)sW4)[(grp * NSM + gs) * NMROW + r0];
                const ulonglong2 wv1 = ((const ulonglong2*)sW4)[(grp * NSM + gs) * NMROW + r1];
                const ulonglong2 q0  = h0v[hb + NGR + gs];
                const ulonglong2 q1  = h1v[hb + NGR + gs];
                FFMA2(a00, wv0.x, q0.x);
                FFMA2(a01, wv0.x, q1.x);
                FFMA2(a10, wv1.x, q0.x);
                FFMA2(a11, wv1.x, q1.x);
                FFMA2(a00, wv0.y, q0.y);
                FFMA2(a01, wv0.y, q1.y);
                FFMA2(a10, wv1.y, q0.y);
                FFMA2(a11, wv1.y, q1.y);
            }
            if (grp == 0) {
                pA[r0] = make_float2(rsum2(a00) + fmaf(xt.x, wih0, bias0),
                                     rsum2(a01) + fmaf(xt.y, wih0, bias0));
                pA[r1] = make_float2(rsum2(a10) + fmaf(xt.x, wih1, bias1),
                                     rsum2(a11) + fmaf(xt.y, wih1, bias1));
            } else {
                pB[r0] = make_float2(rsum2(a00), rsum2(a01));
                pB[r1] = make_float2(rsum2(a10), rsum2(a11));
            }
        } else {
            // warp 7: rows 448,449 k-distributed over 19 lanes (4 k's each)
            float s0a = 0.f, s0b = 0.f, s1a = 0.f, s1b = 0.f;
            if (ly < 19) {
                const float4 q0 = ((const float4*)h0s)[(kb >> 2) + ly];
                const float4 q1 = ((const float4*)h1s)[(kb >> 2) + ly];
                s0a = fmaf(m448[0], q0.x, fmaf(m448[1], q0.y, fmaf(m448[2], q0.z, m448[3] * q0.w)));
                s0b = fmaf(m448[0], q1.x, fmaf(m448[1], q1.y, fmaf(m448[2], q1.z, m448[3] * q1.w)));
                s1a = fmaf(m449[0], q0.x, fmaf(m449[1], q0.y, fmaf(m449[2], q0.z, m449[3] * q0.w)));
                s1b = fmaf(m449[0], q1.x, fmaf(m449[1], q1.y, fmaf(m449[2], q1.z, m449[3] * q1.w)));
            }
            #pragma unroll
            for (int d = 16; d > 0; d >>= 1) {
                s0a += __shfl_xor_sync(0xffffffffu, s0a, d);
                s0b += __shfl_xor_sync(0xffffffffu, s0b, d);
                s1a += __shfl_xor_sync(0xffffffffu, s1a, d);
                s1b += __shfl_xor_sync(0xffffffffu, s1b, d);
            }
            if (ly == 0) {
                if (grp == 0) {
                    pA[448] = make_float2(s0a + b448, s0b + b448);
                    pA[449] = make_float2(s1a + b449, s1b + b449);
                } else {
                    pB[448] = make_float2(s0a, s0b);
                    pB[449] = make_float2(s1a, s1b);
                }
            }
        }
        __syncthreads();

        // gate stage: group g's threads lt<150 handle batch g, unit lt
        if (lt < HID) {
            const float xb = grp ? xt.y : xt.x;
            float*      hs = grp ? h1s : h0s;
            float*      yb = grp ? y1  : y0;

            const float2 vr = pA[lt];
            const float2 wr_ = pB[lt];
            const float2 vz = pA[lt + HID];
            const float2 wz = pB[lt + HID];
            const float2 vn = pA[lt + 2 * HID];
            const float2 wn = pB[lt + 2 * HID];

            const float gr = grp ? (vr.y + wr_.y) : (vr.x + wr_.x);
            const float gz = grp ? (vz.y + wz.y) : (vz.x + wz.x);
            const float gn = grp ? (vn.y + wn.y) : (vn.x + wn.x);
            const float h  = hs[lt];

            const float in = fmaf(xb, win, bin);
            const float r  = sigt(gr);
            const float z  = sigt(gz);
            const float n  = tanhacc(fmaf(r, gn, in));
            const float hn = fmaxf(0.0f, fmaf(z, h - n, n));

            hs[lt] = hn;
            yb[lt] = hn * wlin;
        }
        __syncthreads();

        // y head: each group's warp 7 reduces its batch (overlaps next matvec)
        if (!mainw) {
            const float* yb = grp ? y1 : y0;
            float s = yb[ly] + yb[ly + 32] + yb[ly + 64] + yb[ly + 96]
                    + ((ly + 128 < HID) ? yb[ly + 128] : 0.0f);
            s += __shfl_xor_sync(0xffffffffu, s, 16);
            s += __shfl_xor_sync(0xffffffffu, s, 8);
            s += __shfl_xor_sync(0xffffffffu, s, 4);
            s += __shfl_xor_sync(0xffffffffu, s, 2);
            s += __shfl_xor_sync(0xffffffffu, s, 1);
            if (ly == 0) (grp ? or1 : or0)[t] = s + bl;
        }
    }
}

extern "C" void kernel_launch(void* const* d_in, const int* in_sizes, int n_in,
                              void* d_out, int out_size) {
    const float* x    = (const float*)d_in[0];
    const float* Wih  = (const float*)d_in[1];
    const float* Whh  = (const float*)d_in[2];
    const float* bih  = (const float*)d_in[3];
    const float* bhh  = (const float*)d_in[4];
    const float* Wlin = (const float*)d_in[5];
    const float* blin = (const float*)d_in[6];
    float* out = (float*)d_out;

    const size_t smem_bytes = SMEM_FLOATS * sizeof(float);   // 169,536 B
    cudaFuncSetAttribute(gru_persistent,
                         cudaFuncAttributeMaxDynamicSharedMemorySize,
                         (int)smem_bytes);

    gru_persistent<<<128, NTH, smem_bytes>>>(x, Wih, Whh, bih, bhh, Wlin, blin, out);
}

// round 11
// speedup vs baseline: 2.9434x; 1.0356x over previous
#include <cuda_runtime.h>
#include <math.h>

// GRU recurrence, persistent kernel, round 8: wavefront cut (KRH=40) +
// interleaved load/FMA schedule + full-MUFU gate.
// B=256, T=2048, H=150 (3H=450 gate rows), I=O=1.
// 128 CTAs x 512 threads; CTA owns batches (2*cta, 2*cta+1).
// Two K-half groups of 256 threads: grp 0 k=0..75, grp 1 k=76..151.
// Warps 0-6 per group (lt<224): rows lt, lt+224 (rows 0..447).
// Warp 7 per group: rows 448/449 mini-matvec + y-head.
// Per main thread: 40 W floats/row in regs (f32x2 pairs), 36/row in SMEM.

#define NTH     512
#define NGRP    256
#define HID     150
#define G2      300
#define TLEN    2048
#define KH      76         // K per half (152 padded)
#define KRH     40         // reg W floats per half-row (20 u64)
#define NGR     10         // 4-float reg k-groups
#define NSM     9          // 4-float smem k-groups (36 floats)
#define NMROW   448        // rows covered by main warps

// SMEM layout (floats):
#define OFF_SW   0                          // float4 [2*NSM][448] = 32256 floats
#define OFF_SX   (2*NSM*NMROW*4)            // float2[2048] = 4096
#define OFF_H0   (OFF_SX + 2*TLEN)          // 160
#define OFF_H1   (OFF_H0 + 160)             // 160
#define OFF_PA   (OFF_H1 + 160)             // float2[452] = 904
#define OFF_PB   (OFF_PA + 904)             // float2[452] = 904
#define OFF_Y0   (OFF_PB + 904)             // 160
#define OFF_Y1   (OFF_Y0 + 160)             // 160
#define SMEM_FLOATS (OFF_Y1 + 160)          // 38800 floats = 155,200 B

typedef unsigned long long u64;

#define FFMA2(d, a, b) asm("fma.rn.f32x2 %0, %1, %2, %0;" : "+l"(d) : "l"(a), "l"(b))

__device__ __forceinline__ u64 pack2(float a, float b) {
    u64 r; asm("mov.b64 %0, {%1, %2};" : "=l"(r) : "f"(a), "f"(b)); return r;
}
__device__ __forceinline__ float rsum2(u64 v) {
    float lo, hi; asm("mov.b64 {%0, %1}, %2;" : "=f"(lo), "=f"(hi) : "l"(v));
    return lo + hi;
}
__device__ __forceinline__ float tanha(float x) {       // MUFU.TANH
    float y; asm("tanh.approx.f32 %0, %1;" : "=f"(y) : "f"(x)); return y;
}
__device__ __forceinline__ float sigt(float v) {        // sigmoid via tanh.approx
    return fmaf(0.5f, tanha(0.5f * v), 0.5f);
}

extern "C" __global__ void __launch_bounds__(NTH, 1)
gru_persistent(const float* __restrict__ x,     // [B][T]
               const float* __restrict__ Wih,   // [450][1]
               const float* __restrict__ Whh,   // [450][150]
               const float* __restrict__ bih,   // [450]
               const float* __restrict__ bhh,   // [450]
               const float* __restrict__ Wlin,  // [1][150]
               const float* __restrict__ blin,  // [1]
               float* __restrict__ out)         // [B][T]
{
    extern __shared__ float smem[];
    float4* sW4 = (float4*)(smem + OFF_SW);     // [(grp*NSM+gs)*448 + row]
    float2* sxp = (float2*)(smem + OFF_SX);     // (x_b0, x_b1) per t
    float*  h0s = smem + OFF_H0;
    float*  h1s = smem + OFF_H1;
    float2* pA  = (float2*)(smem + OFF_PA);     // group A partial, (b0,b1)/row
    float2* pB  = (float2*)(smem + OFF_PB);
    float*  y0  = smem + OFF_Y0;
    float*  y1  = smem + OFF_Y1;

    const int tid  = threadIdx.x;
    const int grp  = tid >> 8;            // 0: k=0..75,  1: k=76..151
    const int lt   = tid & (NGRP - 1);
    const int b0   = blockIdx.x * 2;
    const int kb   = grp * KH;
    const bool mainw = (lt < 224);
    const int r0   = lt;
    const int ly   = lt - 224;            // warp-7 lane role

    // Base pointers folded per-thread so loop LDS use [reg + imm] only.
    const ulonglong2* wbase = (const ulonglong2*)sW4 + (size_t)grp * NSM * NMROW + r0;
    const ulonglong2* q0b   = (const ulonglong2*)h0s + grp * (KH / 4);
    const ulonglong2* q1b   = (const ulonglong2*)h1s + grp * (KH / 4);

    // ---------------- init ----------------
    u64 w0[KRH / 2], w1[KRH / 2];         // main-thread reg W (packed k-pairs)
    float m448[4], m449[4];               // warp-7 mini W
    float b448 = 0.0f, b449 = 0.0f;

    if (mainw) {
        const float* wr0 = Whh + r0 * HID + kb;
        const float* wr1 = Whh + (r0 + 224) * HID + kb;
        #pragma unroll
        for (int p = 0; p < KRH / 2; p++) {       // k = kb..kb+39 < 150 always
            w0[p] = pack2(wr0[2 * p], wr0[2 * p + 1]);
            w1[p] = pack2(wr1[2 * p], wr1[2 * p + 1]);
        }
        #pragma unroll
        for (int gs = 0; gs < NSM; gs++) {        // k = kb+40 .. kb+75 (pad>=150)
            int k = KRH + 4 * gs;
            float4 v0, v1;
            v0.x = (kb + k + 0 < HID) ? wr0[k + 0] : 0.0f;
            v0.y = (kb + k + 1 < HID) ? wr0[k + 1] : 0.0f;
            v0.z = (kb + k + 2 < HID) ? wr0[k + 2] : 0.0f;
            v0.w = (kb + k + 3 < HID) ? wr0[k + 3] : 0.0f;
            v1.x = (kb + k + 0 < HID) ? wr1[k + 0] : 0.0f;
            v1.y = (kb + k + 1 < HID) ? wr1[k + 1] : 0.0f;
            v1.z = (kb + k + 2 < HID) ? wr1[k + 2] : 0.0f;
            v1.w = (kb + k + 3 < HID) ? wr1[k + 3] : 0.0f;
            sW4[(grp * NSM + gs) * NMROW + r0]       = v0;
            sW4[(grp * NSM + gs) * NMROW + r0 + 224] = v1;
        }
    } else {
        #pragma unroll
        for (int j = 0; j < 4; j++) {
            int k = kb + 4 * ly + j;               // valid work ly<19
            bool ok = (ly < 19) && (k < HID);
            m448[j] = ok ? Whh[448 * HID + k] : 0.0f;
            m449[j] = ok ? Whh[449 * HID + k] : 0.0f;
        }
        b448 = bhh[448];
        b449 = bhh[449];
    }

    // Per-row input weight / bias (added by group A only).
    float wih0 = 0.0f, bias0 = 0.0f, wih1 = 0.0f, bias1 = 0.0f;
    if (grp == 0 && mainw) {
        const int r1 = r0 + 224;
        wih0  = (r0 < G2) ? Wih[r0] : 0.0f;
        bias0 = (r0 < G2) ? (bih[r0] + bhh[r0]) : bhh[r0];
        wih1  = (r1 < G2) ? Wih[r1] : 0.0f;
        bias1 = (r1 < G2) ? (bih[r1] + bhh[r1]) : bhh[r1];
    }

    // Gate-stage constants (lt < 150; group g handles batch g)
    float win = 0.0f, bin = 0.0f, wlin = 0.0f;
    if (lt < HID) {
        win  = Wih[2 * HID + lt];
        bin  = bih[2 * HID + lt];
        wlin = Wlin[lt];
    }
    const float bl = __ldg(blin);

    // Stage x (packed per-t), zero h (incl. pads)
    {
        const float* xr0 = x + (size_t)b0 * TLEN;
        const float* xr1 = x + (size_t)(b0 + 1) * TLEN;
        for (int i = tid; i < TLEN; i += NTH) sxp[i] = make_float2(xr0[i], xr1[i]);
        for (int i = tid; i < 160;  i += NTH) { h0s[i] = 0.0f; h1s[i] = 0.0f; }
    }
    __syncthreads();

    float* or0 = out + (size_t)b0 * TLEN;
    float* or1 = out + (size_t)(b0 + 1) * TLEN;

    // ---------------- time loop ----------------
    for (int t = 0; t < TLEN; t++) {
        const float2 xt = sxp[t];

        if (mainw) {
            u64 a00 = 0, a01 = 0, a10 = 0, a11 = 0;   // a[row][batch]
            // Fused schedule: per iteration load the W-smem pair first, run the
            // (load-independent) reg-group FFMA2s, then consume the W pair.
            #pragma unroll
            for (int g = 0; g < NSM; g++) {
                const ulonglong2 wv0 = wbase[g * NMROW];
                const ulonglong2 wv1 = wbase[g * NMROW + 224];
                const ulonglong2 qr0 = q0b[g];
                const ulonglong2 qr1 = q1b[g];
                // reg k-group g
                FFMA2(a00, w0[2 * g],     qr0.x);
                FFMA2(a01, w0[2 * g],     qr1.x);
                FFMA2(a10, w1[2 * g],     qr0.x);
                FFMA2(a11, w1[2 * g],     qr1.x);
                FFMA2(a00, w0[2 * g + 1], qr0.y);
                FFMA2(a01, w0[2 * g + 1], qr1.y);
                FFMA2(a10, w1[2 * g + 1], qr0.y);
                FFMA2(a11, w1[2 * g + 1], qr1.y);
                // smem k-group g (k = kb+40+4g)
                const ulonglong2 qs0 = q0b[NGR + g];
                const ulonglong2 qs1 = q1b[NGR + g];
                FFMA2(a00, wv0.x, qs0.x);
                FFMA2(a01, wv0.x, qs1.x);
                FFMA2(a10, wv1.x, qs0.x);
                FFMA2(a11, wv1.x, qs1.x);
                FFMA2(a00, wv0.y, qs0.y);
                FFMA2(a01, wv0.y, qs1.y);
                FFMA2(a10, wv1.y, qs0.y);
                FFMA2(a11, wv1.y, qs1.y);
            }
            {   // final reg k-group (g = NGR-1 = 9)
                const ulonglong2 qr0 = q0b[NGR - 1];
                const ulonglong2 qr1 = q1b[NGR - 1];
                FFMA2(a00, w0[2 * (NGR - 1)],     qr0.x);
                FFMA2(a01, w0[2 * (NGR - 1)],     qr1.x);
                FFMA2(a10, w1[2 * (NGR - 1)],     qr0.x);
                FFMA2(a11, w1[2 * (NGR - 1)],     qr1.x);
                FFMA2(a00, w0[2 * (NGR - 1) + 1], qr0.y);
                FFMA2(a01, w0[2 * (NGR - 1) + 1], qr1.y);
                FFMA2(a10, w1[2 * (NGR - 1) + 1], qr0.y);
                FFMA2(a11, w1[2 * (NGR - 1) + 1], qr1.y);
            }
            if (grp == 0) {
                pA[r0]       = make_float2(rsum2(a00) + fmaf(xt.x, wih0, bias0),
                                           rsum2(a01) + fmaf(xt.y, wih0, bias0));
                pA[r0 + 224] = make_float2(rsum2(a10) + fmaf(xt.x, wih1, bias1),
                                           rsum2(a11) + fmaf(xt.y, wih1, bias1));
            } else {
                pB[r0]       = make_float2(rsum2(a00), rsum2(a01));
                pB[r0 + 224] = make_float2(rsum2(a10), rsum2(a11));
            }
        } else {
            // warp 7: rows 448,449 k-distributed over 19 lanes (4 k's each)
            float s0a = 0.f, s0b = 0.f, s1a = 0.f, s1b = 0.f;
            if (ly < 19) {
                const float4 q0 = ((const float4*)h0s)[(kb >> 2) + ly];
                const float4 q1 = ((const float4*)h1s)[(kb >> 2) + ly];
                s0a = fmaf(m448[0], q0.x, fmaf(m448[1], q0.y, fmaf(m448[2], q0.z, m448[3] * q0.w)));
                s0b = fmaf(m448[0], q1.x, fmaf(m448[1], q1.y, fmaf(m448[2], q1.z, m448[3] * q1.w)));
                s1a = fmaf(m449[0], q0.x, fmaf(m449[1], q0.y, fmaf(m449[2], q0.z, m449[3] * q0.w)));
                s1b = fmaf(m449[0], q1.x, fmaf(m449[1], q1.y, fmaf(m449[2], q1.z, m449[3] * q1.w)));
            }
            #pragma unroll
            for (int d = 16; d > 0; d >>= 1) {
                s0a += __shfl_xor_sync(0xffffffffu, s0a, d);
                s0b += __shfl_xor_sync(0xffffffffu, s0b, d);
                s1a += __shfl_xor_sync(0xffffffffu, s1a, d);
                s1b += __shfl_xor_sync(0xffffffffu, s1b, d);
            }
            if (ly == 0) {
                if (grp == 0) {
                    pA[448] = make_float2(s0a + b448, s0b + b448);
                    pA[449] = make_float2(s1a + b449, s1b + b449);
                } else {
                    pB[448] = make_float2(s0a, s0b);
                    pB[449] = make_float2(s1a, s1b);
                }
            }
        }
        __syncthreads();

        // gate stage: group g's threads lt<150 handle batch g, unit lt
        if (lt < HID) {
            const float xb = grp ? xt.y : xt.x;
            float*      hs = grp ? h1s : h0s;
            float*      yb = grp ? y1  : y0;

            const float2 vr  = pA[lt];
            const float2 wr_ = pB[lt];
            const float2 vz  = pA[lt + HID];
            const float2 wz  = pB[lt + HID];
            const float2 vn  = pA[lt + 2 * HID];
            const float2 wn  = pB[lt + 2 * HID];

            const float gr = grp ? (vr.y + wr_.y) : (vr.x + wr_.x);
            const float gz = grp ? (vz.y + wz.y) : (vz.x + wz.x);
            const float gn = grp ? (vn.y + wn.y) : (vn.x + wn.x);
            const float h  = hs[lt];

            const float in = fmaf(xb, win, bin);
            const float r  = sigt(gr);
            const float z  = sigt(gz);
            const float n  = tanha(fmaf(r, gn, in));
            const float hn = fmaxf(0.0f, fmaf(z, h - n, n));

            hs[lt] = hn;
            yb[lt] = hn * wlin;
        }
        __syncthreads();

        // y head: each group's warp 7 reduces its batch (overlaps next matvec)
        if (!mainw) {
            const float* yb = grp ? y1 : y0;
            float s = yb[ly] + yb[ly + 32] + yb[ly + 64] + yb[ly + 96]
                    + ((ly + 128 < HID) ? yb[ly + 128] : 0.0f);
            s += __shfl_xor_sync(0xffffffffu, s, 16);
            s += __shfl_xor_sync(0xffffffffu, s, 8);
            s += __shfl_xor_sync(0xffffffffu, s, 4);
            s += __shfl_xor_sync(0xffffffffu, s, 2);
            s += __shfl_xor_sync(0xffffffffu, s, 1);
            if (ly == 0) (grp ? or1 : or0)[t] = s + bl;
        }
    }
}

extern "C" void kernel_launch(void* const* d_in, const int* in_sizes, int n_in,
                              void* d_out, int out_size) {
    const float* x    = (const float*)d_in[0];
    const float* Wih  = (const float*)d_in[1];
    const float* Whh  = (const float*)d_in[2];
    const float* bih  = (const float*)d_in[3];
    const float* bhh  = (const float*)d_in[4];
    const float* Wlin = (const float*)d_in[5];
    const float* blin = (const float*)d_in[6];
    float* out = (float*)d_out;

    const size_t smem_bytes = SMEM_FLOATS * sizeof(float);   // 155,200 B
    cudaFuncSetAttribute(gru_persistent,
                         cudaFuncAttributeMaxDynamicSharedMemorySize,
                         (int)smem_bytes);

    gru_persistent<<<128, NTH, smem_bytes>>>(x, Wih, Whh, bih, bhh, Wlin, blin, out);
}